// round 2
// baseline (speedup 1.0000x reference)
#include <cuda_runtime.h>
#include <cuda_bf16.h>
#include <cstdint>

#define BSZ 2
#define LQ 2048
#define DM 256
#define NHEAD 4
#define HDIM 64
#define MROWS (BSZ*LQ)   // 4096

// scratch (static device arrays: allocation-free)
__device__ float g_Q[MROWS*DM];
__device__ float g_K[MROWS*DM];
__device__ float g_V[MROWS*DM];
__device__ float g_O[MROWS*DM];
__device__ float g_msg[MROWS*DM];
__device__ float g_hid[MROWS*2*DM];

// ---------------------------------------------------------------------------
// QKV projection: C = (A1 [+A2]) @ B,  M=4096, N=256, K=256
// blockIdx.y selects Q/K/V. 32 rows per CTA, 256 threads, 4x8 micro-tile.
// ---------------------------------------------------------------------------
__global__ void qkv_kernel(const float* __restrict__ x,  const float* __restrict__ xpe,
                           const float* __restrict__ src, const float* __restrict__ spe,
                           const float* __restrict__ Wq, const float* __restrict__ Wk,
                           const float* __restrict__ Wv,
                           float* __restrict__ Q, float* __restrict__ K, float* __restrict__ V)
{
    extern __shared__ float smem[];
    float* As = smem;            // 32*256
    float* Bs = smem + 32*256;   // 16*256

    const float *A1, *A2, *B; float* C;
    int w = blockIdx.y;
    if (w == 0)      { A1 = x;   A2 = xpe;     B = Wq; C = Q; }
    else if (w == 1) { A1 = src; A2 = spe;     B = Wk; C = K; }
    else             { A1 = src; A2 = nullptr; B = Wv; C = V; }

    int tid = threadIdx.x;
    int ng = tid & 31, lg = tid >> 5;
    int row0 = blockIdx.x * 32;

    for (int idx = tid; idx < 32*256; idx += 256) {
        int r = idx >> 8, c = idx & 255;
        float v = A1[(row0 + r)*256 + c];
        if (A2) v += A2[(row0 + r)*256 + c];
        As[idx] = v;
    }

    float acc[4][8];
    #pragma unroll
    for (int i = 0; i < 4; i++)
        #pragma unroll
        for (int j = 0; j < 8; j++) acc[i][j] = 0.f;

    for (int k0 = 0; k0 < 256; k0 += 16) {
        __syncthreads();
        #pragma unroll
        for (int i = 0; i < 16; i++) Bs[i*256 + tid] = B[(k0 + i)*256 + tid];
        __syncthreads();
        #pragma unroll
        for (int k = 0; k < 16; k++) {
            float a[4], b[8];
            #pragma unroll
            for (int il = 0; il < 4; il++) a[il] = As[(lg*4 + il)*256 + k0 + k];
            #pragma unroll
            for (int j = 0; j < 8; j++) b[j] = Bs[k*256 + ng + 32*j];
            #pragma unroll
            for (int il = 0; il < 4; il++)
                #pragma unroll
                for (int j = 0; j < 8; j++) acc[il][j] += a[il]*b[j];
        }
    }
    #pragma unroll
    for (int il = 0; il < 4; il++) {
        int row = row0 + lg*4 + il;
        #pragma unroll
        for (int j = 0; j < 8; j++) C[row*256 + ng + 32*j] = acc[il][j];
    }
}

// ---------------------------------------------------------------------------
// Flash attention, fp32 SIMT. CTA = (batch, 32 query rows), all 4 heads.
// threads: sg = tid&7 (4 s-cols each), lg = (tid>>3)&7 (4 l-rows each), h = tid>>6
// ---------------------------------------------------------------------------
__global__ void attn_kernel(const float* __restrict__ Qm, const float* __restrict__ Km,
                            const float* __restrict__ Vm, const float* __restrict__ comp,
                            const int* __restrict__ xmask, const int* __restrict__ smask,
                            float* __restrict__ O)
{
    const int STR = 258;             // padded row stride (even: float2-aligned)
    extern __shared__ float smem[];
    float* Qs = smem;                // 32*258
    float* Ks = Qs + 32*STR;         // 32*258
    float* Vs = Ks + 32*STR;         // 32*258
    float* Cs = Vs + 32*STR;         // 32*32
    float* Ps = Cs + 32*32;          // 32*137  (layout: [l]*137 + h*34 + s)
    int*   xm  = (int*)(Ps + 32*137);
    int*   sms = xm + 32;

    int tid = threadIdx.x;
    int sg = tid & 7, lg = (tid >> 3) & 7, h = tid >> 6;
    int b = blockIdx.y;
    int l0 = blockIdx.x * 32;
    int row0 = b*LQ + l0;

    for (int idx = tid; idx < 32*256; idx += 256) {
        int r = idx >> 8, c = idx & 255;
        Qs[r*STR + c] = Qm[(row0 + r)*256 + c];
    }
    if (tid < 32) xm[tid] = xmask[b*LQ + l0 + tid];

    float o[4][8];
    #pragma unroll
    for (int i = 0; i < 4; i++)
        #pragma unroll
        for (int j = 0; j < 8; j++) o[i][j] = 0.f;
    float rmax[4] = {-1e38f, -1e38f, -1e38f, -1e38f};
    float rsum[4] = {0.f, 0.f, 0.f, 0.f};

    for (int st = 0; st < LQ/32; st++) {
        int s0 = st * 32;
        __syncthreads();   // prev PV done before overwriting tiles
        for (int idx = tid; idx < 32*256; idx += 256) {
            int r = idx >> 8, c = idx & 255;
            int grow = b*LQ + s0 + r;
            Ks[r*STR + c] = Km[grow*256 + c];
            Vs[r*STR + c] = Vm[grow*256 + c];
        }
        for (int idx = tid; idx < 1024; idx += 256) {
            int r = idx >> 5, c = idx & 31;
            Cs[idx] = comp[(b*LQ + l0 + r)*LQ + s0 + c];
        }
        if (tid < 32) sms[tid] = smask[b*LQ + s0 + tid];
        __syncthreads();

        // scores: 4x4 micro-tile per thread over head h's 64 dims
        float acc[4][4];
        #pragma unroll
        for (int i = 0; i < 4; i++)
            #pragma unroll
            for (int j = 0; j < 4; j++) acc[i][j] = 0.f;
        const float* qb = Qs + h*HDIM;
        const float* kb = Ks + h*HDIM;
        #pragma unroll 8
        for (int d = 0; d < HDIM; d += 2) {
            float2 q2[4], k2[4];
            #pragma unroll
            for (int il = 0; il < 4; il++) q2[il] = *(const float2*)(qb + (lg*4 + il)*STR + d);
            #pragma unroll
            for (int is = 0; is < 4; is++) k2[is] = *(const float2*)(kb + (sg*4 + is)*STR + d);
            #pragma unroll
            for (int il = 0; il < 4; il++)
                #pragma unroll
                for (int is = 0; is < 4; is++) {
                    acc[il][is] += q2[il].x * k2[is].x;
                    acc[il][is] += q2[il].y * k2[is].y;
                }
        }

        // online softmax update (per (l,h) row; 8 sg lanes share a row)
        #pragma unroll
        for (int il = 0; il < 4; il++) {
            int l = lg*4 + il;
            float p[4];
            float tmax = -1e38f;
            #pragma unroll
            for (int is = 0; is < 4; is++) {
                int s = sg*4 + is;
                float v = acc[il][is] * Cs[l*32 + s];
                if (xm[l] && !sms[s]) v = -1e30f;
                v *= 0.125f;     // 1/sqrt(64)
                p[is] = v;
                tmax = fmaxf(tmax, v);
            }
            tmax = fmaxf(tmax, __shfl_xor_sync(0xffffffffu, tmax, 1));
            tmax = fmaxf(tmax, __shfl_xor_sync(0xffffffffu, tmax, 2));
            tmax = fmaxf(tmax, __shfl_xor_sync(0xffffffffu, tmax, 4));
            float mnew = fmaxf(rmax[il], tmax);
            float tsum = 0.f;
            #pragma unroll
            for (int is = 0; is < 4; is++) { p[is] = __expf(p[is] - mnew); tsum += p[is]; }
            tsum += __shfl_xor_sync(0xffffffffu, tsum, 1);
            tsum += __shfl_xor_sync(0xffffffffu, tsum, 2);
            tsum += __shfl_xor_sync(0xffffffffu, tsum, 4);
            float scale = __expf(rmax[il] - mnew);
            rsum[il] = rsum[il]*scale + tsum;
            rmax[il] = mnew;
            #pragma unroll
            for (int dd = 0; dd < 8; dd++) o[il][dd] *= scale;
            #pragma unroll
            for (int is = 0; is < 4; is++) Ps[l*137 + h*34 + sg*4 + is] = p[is];
        }
        // P producer/consumer of each row is the same warp
        __syncwarp();

        // PV: o[l][dd] += P[l][s] * V[s][h*64 + sg*8 + dd]
        const float* vb = Vs + h*HDIM + sg*8;
        #pragma unroll 4
        for (int s = 0; s < 32; s++) {
            float pl[4];
            #pragma unroll
            for (int il = 0; il < 4; il++) pl[il] = Ps[(lg*4 + il)*137 + h*34 + s];
            float2 v0 = *(const float2*)(vb + s*STR + 0);
            float2 v1 = *(const float2*)(vb + s*STR + 2);
            float2 v2 = *(const float2*)(vb + s*STR + 4);
            float2 v3 = *(const float2*)(vb + s*STR + 6);
            #pragma unroll
            for (int il = 0; il < 4; il++) {
                o[il][0] += pl[il]*v0.x; o[il][1] += pl[il]*v0.y;
                o[il][2] += pl[il]*v1.x; o[il][3] += pl[il]*v1.y;
                o[il][4] += pl[il]*v2.x; o[il][5] += pl[il]*v2.y;
                o[il][6] += pl[il]*v3.x; o[il][7] += pl[il]*v3.y;
            }
        }
    }

    #pragma unroll
    for (int il = 0; il < 4; il++) {
        float inv = 1.f / rsum[il];
        int row = row0 + lg*4 + il;
        float* op = O + row*256 + h*HDIM + sg*8;
        #pragma unroll
        for (int dd = 0; dd < 8; dd++) op[dd] = o[il][dd] * inv;
    }
}

// ---------------------------------------------------------------------------
// C = LayerNorm(A @ B) [+ resid].  A: [4096, KDIM], B: [KDIM, 256].
// CTA covers 32 full rows -> LN via warp shuffle (warp = one 4-row group).
// ---------------------------------------------------------------------------
template<int KDIM, bool RESID>
__global__ void rowgemm_ln_kernel(const float* __restrict__ A, const float* __restrict__ B,
                                  const float* __restrict__ gamma, const float* __restrict__ beta,
                                  const float* __restrict__ resid, float* __restrict__ C)
{
    extern __shared__ float smem[];
    float* As = smem;              // 32*KDIM
    float* Bs = smem + 32*KDIM;    // 16*256

    int tid = threadIdx.x;
    int ng = tid & 31, lg = tid >> 5;
    int row0 = blockIdx.x * 32;

    for (int idx = tid; idx < 32*KDIM; idx += 256)
        As[idx] = A[(row0 + (idx / KDIM))*KDIM + (idx % KDIM)];

    float acc[4][8];
    #pragma unroll
    for (int i = 0; i < 4; i++)
        #pragma unroll
        for (int j = 0; j < 8; j++) acc[i][j] = 0.f;

    for (int k0 = 0; k0 < KDIM; k0 += 16) {
        __syncthreads();
        #pragma unroll
        for (int i = 0; i < 16; i++) Bs[i*256 + tid] = B[(k0 + i)*256 + tid];
        __syncthreads();
        #pragma unroll
        for (int k = 0; k < 16; k++) {
            float a[4], b[8];
            #pragma unroll
            for (int il = 0; il < 4; il++) a[il] = As[(lg*4 + il)*KDIM + k0 + k];
            #pragma unroll
            for (int j = 0; j < 8; j++) b[j] = Bs[k*256 + ng + 32*j];
            #pragma unroll
            for (int il = 0; il < 4; il++)
                #pragma unroll
                for (int j = 0; j < 8; j++) acc[il][j] += a[il]*b[j];
        }
    }

    #pragma unroll
    for (int il = 0; il < 4; il++) {
        int row = row0 + lg*4 + il;
        float s1 = 0.f, s2 = 0.f;
        #pragma unroll
        for (int j = 0; j < 8; j++) { s1 += acc[il][j]; s2 += acc[il][j]*acc[il][j]; }
        #pragma unroll
        for (int off = 16; off > 0; off >>= 1) {
            s1 += __shfl_xor_sync(0xffffffffu, s1, off);
            s2 += __shfl_xor_sync(0xffffffffu, s2, off);
        }
        float mean = s1 * (1.f/256.f);
        float var  = s2 * (1.f/256.f) - mean*mean;
        float inv  = rsqrtf(var + 1e-5f);
        #pragma unroll
        for (int j = 0; j < 8; j++) {
            int n = ng + 32*j;
            float r = (acc[il][j] - mean) * inv * gamma[n] + beta[n];
            if (RESID) r += resid[row*256 + n];
            C[row*256 + n] = r;
        }
    }
}

// ---------------------------------------------------------------------------
// hidden = relu(concat([x, msg]) @ Wmlp1).  K=512, N=512 (blockIdx.y = N half)
// ---------------------------------------------------------------------------
__global__ void mlp1_kernel(const float* __restrict__ x, const float* __restrict__ msg,
                            const float* __restrict__ W, float* __restrict__ C)
{
    extern __shared__ float smem[];
    float* As = smem;              // 32*512
    float* Bs = smem + 32*512;     // 16*256

    int tid = threadIdx.x;
    int ng = tid & 31, lg = tid >> 5;
    int row0 = blockIdx.x * 32;
    int n0 = blockIdx.y * 256;

    for (int idx = tid; idx < 32*512; idx += 256) {
        int r = idx >> 9, c = idx & 511;
        As[idx] = (c < 256) ? x[(row0 + r)*256 + c] : msg[(row0 + r)*256 + (c - 256)];
    }

    float acc[4][8];
    #pragma unroll
    for (int i = 0; i < 4; i++)
        #pragma unroll
        for (int j = 0; j < 8; j++) acc[i][j] = 0.f;

    for (int k0 = 0; k0 < 512; k0 += 16) {
        __syncthreads();
        #pragma unroll
        for (int i = 0; i < 16; i++) Bs[i*256 + tid] = W[(k0 + i)*512 + n0 + tid];
        __syncthreads();
        #pragma unroll
        for (int k = 0; k < 16; k++) {
            float a[4], b[8];
            #pragma unroll
            for (int il = 0; il < 4; il++) a[il] = As[(lg*4 + il)*512 + k0 + k];
            #pragma unroll
            for (int j = 0; j < 8; j++) b[j] = Bs[k*256 + ng + 32*j];
            #pragma unroll
            for (int il = 0; il < 4; il++)
                #pragma unroll
                for (int j = 0; j < 8; j++) acc[il][j] += a[il]*b[j];
        }
    }
    #pragma unroll
    for (int il = 0; il < 4; il++) {
        int row = row0 + lg*4 + il;
        #pragma unroll
        for (int j = 0; j < 8; j++)
            C[row*512 + n0 + ng + 32*j] = fmaxf(acc[il][j], 0.f);
    }
}

// ---------------------------------------------------------------------------
extern "C" void kernel_launch(void* const* d_in, const int* in_sizes, int n_in,
                              void* d_out, int out_size)
{
    const float* x     = (const float*)d_in[0];
    const float* src   = (const float*)d_in[1];
    const float* xpe   = (const float*)d_in[2];
    const float* spe   = (const float*)d_in[3];
    const int* xmask   = (const int*)d_in[4];
    const int* smask   = (const int*)d_in[5];
    const float* comp  = (const float*)d_in[6];
    const float* Wq    = (const float*)d_in[7];
    const float* Wk    = (const float*)d_in[8];
    const float* Wv    = (const float*)d_in[9];
    const float* Wmg   = (const float*)d_in[10];
    const float* Wm1   = (const float*)d_in[11];
    const float* Wm2   = (const float*)d_in[12];
    const float* ln1g  = (const float*)d_in[13];
    const float* ln1b  = (const float*)d_in[14];
    const float* ln2g  = (const float*)d_in[15];
    const float* ln2b  = (const float*)d_in[16];
    float* out = (float*)d_out;

    float *Qp, *Kp, *Vp, *Op, *Mp, *Hp;
    cudaGetSymbolAddress((void**)&Qp, g_Q);
    cudaGetSymbolAddress((void**)&Kp, g_K);
    cudaGetSymbolAddress((void**)&Vp, g_V);
    cudaGetSymbolAddress((void**)&Op, g_O);
    cudaGetSymbolAddress((void**)&Mp, g_msg);
    cudaGetSymbolAddress((void**)&Hp, g_hid);

    const int SM_GEMM256 = (32*256 + 16*256) * 4;   // 49152
    const int SM_GEMM512 = (32*512 + 16*256) * 4;   // 81920
    const int SM_ATTN    = (3*32*258 + 32*32 + 32*137) * 4 + 64*4;  // ~121 KB

    cudaFuncSetAttribute(qkv_kernel,  cudaFuncAttributeMaxDynamicSharedMemorySize, SM_GEMM256);
    cudaFuncSetAttribute(attn_kernel, cudaFuncAttributeMaxDynamicSharedMemorySize, SM_ATTN);
    cudaFuncSetAttribute(rowgemm_ln_kernel<256, false>, cudaFuncAttributeMaxDynamicSharedMemorySize, SM_GEMM256);
    cudaFuncSetAttribute(rowgemm_ln_kernel<512, true>,  cudaFuncAttributeMaxDynamicSharedMemorySize, SM_GEMM512);
    cudaFuncSetAttribute(mlp1_kernel, cudaFuncAttributeMaxDynamicSharedMemorySize, SM_GEMM512);

    qkv_kernel<<<dim3(MROWS/32, 3, 1), 256, SM_GEMM256>>>(x, xpe, src, spe, Wq, Wk, Wv, Qp, Kp, Vp);
    attn_kernel<<<dim3(LQ/32, BSZ, 1), 256, SM_ATTN>>>(Qp, Kp, Vp, comp, xmask, smask, Op);
    rowgemm_ln_kernel<256, false><<<MROWS/32, 256, SM_GEMM256>>>(Op, Wmg, ln1g, ln1b, nullptr, Mp);
    mlp1_kernel<<<dim3(MROWS/32, 2, 1), 256, SM_GEMM512>>>(x, Mp, Wm1, Hp);
    rowgemm_ln_kernel<512, true><<<MROWS/32, 256, SM_GEMM512>>>(Hp, Wm2, ln2g, ln2b, x, out);
}

// round 3
// speedup vs baseline: 2.8907x; 2.8907x over previous
#include <cuda_runtime.h>
#include <cstdint>

#define BSZ 2
#define LQ 2048
#define DM 256
#define MROWS (BSZ*LQ)

// scratch
__device__ float g_Q[MROWS*DM];
__device__ float g_K[MROWS*DM];
__device__ float g_V[MROWS*DM];
__device__ float g_O[MROWS*DM];
__device__ float g_msg[MROWS*DM];
__device__ float g_hid[MROWS*2*DM];

// ---------------------------------------------------------------------------
__device__ __forceinline__ unsigned f2tf(float x){
    unsigned u; asm("cvt.rna.tf32.f32 %0,%1;" : "=r"(u) : "f"(x)); return u;
}
__device__ __forceinline__ void mma8(float* c, const unsigned* a, const unsigned* b){
    asm volatile("mma.sync.aligned.m16n8k8.row.col.f32.tf32.tf32.f32 "
        "{%0,%1,%2,%3},{%4,%5,%6,%7},{%8,%9},{%0,%1,%2,%3};"
        : "+f"(c[0]), "+f"(c[1]), "+f"(c[2]), "+f"(c[3])
        : "r"(a[0]), "r"(a[1]), "r"(a[2]), "r"(a[3]), "r"(b[0]), "r"(b[1]));
}
// e^x for x <= 0, FMA-pipe only (no MUFU). rel err ~2e-6.
__device__ __forceinline__ float fast_exp(float x){
    float y = x * 1.44269504f;
    y = fmaxf(y, -126.0f);
    float z = y + 12582912.0f;                 // 1.5*2^23 round-to-int
    int   n = __float_as_int(z) - 0x4B400000;
    float f = y - (z - 12582912.0f);           // f in [-0.5, 0.5]
    float p = 1.33336e-3f;
    p = fmaf(p, f, 9.61813e-3f);
    p = fmaf(p, f, 5.55041e-2f);
    p = fmaf(p, f, 2.40227e-1f);
    p = fmaf(p, f, 6.93147e-1f);
    p = fmaf(p, f, 1.0f);
    return p * __int_as_float((n + 127) << 23);
}

// ---------------------------------------------------------------------------
// tf32 GEMM: C[M=4096, N(=256 slice)] = A @ B, BM=64, BN=256, BK=32
// 256 threads, 8 warps (wm 0..1 x wn 0..3), warp tile 32x64, frag 2x8 m16n8.
// ---------------------------------------------------------------------------
#define AM_PLAIN 0
#define AM_ADD   1
#define AM_CAT   2
#define EPI_NONE 0
#define EPI_RELU 1
#define EPI_LN   2
#define EPI_LNR  3

#define AS_STR 36
#define BS_STR 264

template<int KD, int AM, int EPI>
__device__ __forceinline__ void gemm_body(
    const float* __restrict__ A1, const float* __restrict__ A2,
    const float* __restrict__ B, int ldb, int n0,
    const float* __restrict__ gamma, const float* __restrict__ beta,
    const float* __restrict__ resid, float* __restrict__ C, int ldc)
{
    extern __shared__ unsigned smu[];
    unsigned* As = smu;                 // 64 x 36
    unsigned* Bs = smu + 64*AS_STR;     // 32 x 264

    int tid = threadIdx.x;
    int w = tid >> 5, lane = tid & 31;
    int wm = w >> 2, wn = w & 3;
    int g4 = lane >> 2, tig = lane & 3;
    int row0 = blockIdx.x * 64;

    float acc[2][8][4];
    #pragma unroll
    for (int mt = 0; mt < 2; mt++)
        #pragma unroll
        for (int nt = 0; nt < 8; nt++)
            #pragma unroll
            for (int i = 0; i < 4; i++) acc[mt][nt][i] = 0.f;

    for (int kc = 0; kc < KD/32; kc++){
        __syncthreads();
        // A chunk 64x32
        #pragma unroll
        for (int i = 0; i < 2; i++){
            int id = tid + i*256;
            int r = id >> 3, c4 = (id & 7) << 2;
            int col = kc*32 + c4;
            float4 v;
            if (AM == AM_ADD){
                float4 x1 = *(const float4*)(A1 + (row0+r)*KD + col);
                float4 x2 = *(const float4*)(A2 + (row0+r)*KD + col);
                v = make_float4(x1.x+x2.x, x1.y+x2.y, x1.z+x2.z, x1.w+x2.w);
            } else if (AM == AM_CAT){
                const float* src = (col < 256) ? (A1 + (row0+r)*256 + col)
                                               : (A2 + (row0+r)*256 + (col-256));
                v = *(const float4*)src;
            } else {
                v = *(const float4*)(A1 + (row0+r)*KD + col);
            }
            unsigned* d = &As[r*AS_STR + c4];
            d[0]=f2tf(v.x); d[1]=f2tf(v.y); d[2]=f2tf(v.z); d[3]=f2tf(v.w);
        }
        // B chunk 32x256
        #pragma unroll
        for (int i = 0; i < 8; i++){
            int id = tid + i*256;
            int r = id >> 6, c4 = (id & 63) << 2;
            float4 v = *(const float4*)(B + (kc*32 + r)*ldb + n0 + c4);
            unsigned* d = &Bs[r*BS_STR + c4];
            d[0]=f2tf(v.x); d[1]=f2tf(v.y); d[2]=f2tf(v.z); d[3]=f2tf(v.w);
        }
        __syncthreads();
        #pragma unroll
        for (int kk = 0; kk < 4; kk++){
            int k0 = kk*8;
            unsigned a[2][4], bf[8][2];
            #pragma unroll
            for (int mt = 0; mt < 2; mt++){
                int r = wm*32 + mt*16 + g4;
                a[mt][0] = As[r*AS_STR + k0 + tig];
                a[mt][1] = As[(r+8)*AS_STR + k0 + tig];
                a[mt][2] = As[r*AS_STR + k0 + tig + 4];
                a[mt][3] = As[(r+8)*AS_STR + k0 + tig + 4];
            }
            #pragma unroll
            for (int nt = 0; nt < 8; nt++){
                int n = wn*64 + nt*8 + g4;
                bf[nt][0] = Bs[(k0 + tig)*BS_STR + n];
                bf[nt][1] = Bs[(k0 + tig + 4)*BS_STR + n];
            }
            #pragma unroll
            for (int mt = 0; mt < 2; mt++)
                #pragma unroll
                for (int nt = 0; nt < 8; nt++)
                    mma8(acc[mt][nt], a[mt], bf[nt]);
        }
    }

    if (EPI == EPI_NONE || EPI == EPI_RELU){
        #pragma unroll
        for (int mt = 0; mt < 2; mt++){
            int rl = row0 + wm*32 + mt*16 + g4;
            #pragma unroll
            for (int nt = 0; nt < 8; nt++){
                int col = n0 + wn*64 + nt*8 + 2*tig;
                float v0 = acc[mt][nt][0], v1 = acc[mt][nt][1];
                float v2 = acc[mt][nt][2], v3 = acc[mt][nt][3];
                if (EPI == EPI_RELU){
                    v0=fmaxf(v0,0.f); v1=fmaxf(v1,0.f); v2=fmaxf(v2,0.f); v3=fmaxf(v3,0.f);
                }
                *(float2*)(C + rl*ldc + col)     = make_float2(v0, v1);
                *(float2*)(C + (rl+8)*ldc + col) = make_float2(v2, v3);
            }
        }
    } else {
        __syncthreads();
        float2* red = (float2*)smu;   // red[64][4]
        float s1[2][2] = {{0,0},{0,0}}, s2[2][2] = {{0,0},{0,0}};
        #pragma unroll
        for (int mt = 0; mt < 2; mt++)
            #pragma unroll
            for (int nt = 0; nt < 8; nt++){
                float c0=acc[mt][nt][0], c1=acc[mt][nt][1], c2=acc[mt][nt][2], c3=acc[mt][nt][3];
                s1[mt][0] += c0+c1; s2[mt][0] += c0*c0 + c1*c1;
                s1[mt][1] += c2+c3; s2[mt][1] += c2*c2 + c3*c3;
            }
        #pragma unroll
        for (int mt = 0; mt < 2; mt++)
            #pragma unroll
            for (int hb = 0; hb < 2; hb++){
                float v1 = s1[mt][hb], v2 = s2[mt][hb];
                v1 += __shfl_xor_sync(~0u, v1, 1); v1 += __shfl_xor_sync(~0u, v1, 2);
                v2 += __shfl_xor_sync(~0u, v2, 1); v2 += __shfl_xor_sync(~0u, v2, 2);
                if (tig == 0){
                    int r = wm*32 + mt*16 + g4 + hb*8;
                    red[r*4 + wn] = make_float2(v1, v2);
                }
            }
        __syncthreads();
        #pragma unroll
        for (int mt = 0; mt < 2; mt++)
            #pragma unroll
            for (int hb = 0; hb < 2; hb++){
                int r = wm*32 + mt*16 + g4 + hb*8;
                float S1=0.f, S2=0.f;
                #pragma unroll
                for (int j = 0; j < 4; j++){ float2 e = red[r*4+j]; S1 += e.x; S2 += e.y; }
                float mean = S1 * (1.f/256.f);
                float var  = S2 * (1.f/256.f) - mean*mean;
                float inv  = rsqrtf(var + 1e-5f);
                int grow = row0 + r;
                #pragma unroll
                for (int nt = 0; nt < 8; nt++){
                    int col = wn*64 + nt*8 + 2*tig;
                    float c0 = acc[mt][nt][hb*2], c1 = acc[mt][nt][hb*2+1];
                    float o0 = (c0 - mean)*inv*gamma[col]   + beta[col];
                    float o1 = (c1 - mean)*inv*gamma[col+1] + beta[col+1];
                    if (EPI == EPI_LNR){
                        o0 += resid[grow*256 + col];
                        o1 += resid[grow*256 + col + 1];
                    }
                    *(float2*)(C + grow*ldc + col) = make_float2(o0, o1);
                }
            }
    }
}

__global__ void __launch_bounds__(256) k_qkv(
    const float* x, const float* xpe, const float* src, const float* spe,
    const float* Wq, const float* Wk, const float* Wv)
{
    if (blockIdx.z == 0)      gemm_body<256, AM_ADD,   EPI_NONE>(x,   xpe, Wq, 256, 0, 0,0,0, g_Q, 256);
    else if (blockIdx.z == 1) gemm_body<256, AM_ADD,   EPI_NONE>(src, spe, Wk, 256, 0, 0,0,0, g_K, 256);
    else                      gemm_body<256, AM_PLAIN, EPI_NONE>(src, 0,   Wv, 256, 0, 0,0,0, g_V, 256);
}
__global__ void __launch_bounds__(256) k_merge(const float* Wmg, const float* gg, const float* bb){
    gemm_body<256, AM_PLAIN, EPI_LN>(g_O, 0, Wmg, 256, 0, gg, bb, 0, g_msg, 256);
}
__global__ void __launch_bounds__(256) k_mlp1(const float* x, const float* Wm1){
    gemm_body<512, AM_CAT, EPI_RELU>(x, g_msg, Wm1, 512, blockIdx.y*256, 0,0,0, g_hid, 512);
}
__global__ void __launch_bounds__(256) k_mlp2(const float* Wm2, const float* gg, const float* bb,
                                              const float* x, float* out){
    gemm_body<512, AM_PLAIN, EPI_LNR>(g_hid, 0, Wm2, 256, 0, gg, bb, x, out, 256);
}

// ---------------------------------------------------------------------------
// Flash attention, tf32 mma. CTA = (b, 32 l-rows), 8 warps.
// warp w: head h = w&3, group g = w>>2. Groups split-KV (s-tiles g, g+2, ...)
// with independent online softmax, merged in epilogue.
// ---------------------------------------------------------------------------
#define QK_STR 260
#define V_STR  264
#define C_STR  33
#define P_STR  34

// smem word offsets
#define OFF_K   8320          // after Qs (32*260)
#define OFF_V   24960         // after Ks  (2*8320)
#define OFF_C   41856         // after Vs  (2*8448)
#define OFF_P   43968         // after Cs  (2*1056)
#define OFF_SM  52672         // after Ps  (8*1088)
#define OFF_SS  52928
#define OFF_XM  53184
#define OFF_SMS 53216
#define ATTN_SMEM_WORDS 53280

__global__ void __launch_bounds__(256) k_attn(
    const float* __restrict__ Qm, const float* __restrict__ Km, const float* __restrict__ Vm,
    const float* __restrict__ comp, const int* __restrict__ xmask, const int* __restrict__ smask,
    float* __restrict__ O)
{
    extern __shared__ float sm[];
    int tid = threadIdx.x;
    int w = tid >> 5, lane = tid & 31;
    int h = w & 3, g = w >> 2;
    int g4 = lane >> 2, tig = lane & 3;
    int gt = tid & 127;
    int b = blockIdx.y, l0 = blockIdx.x * 32;
    int dbase = h*64;

    unsigned* Qs = (unsigned*)sm;
    unsigned* Kg = (unsigned*)sm + OFF_K + g*8320;
    unsigned* Vg = (unsigned*)sm + OFF_V + g*8448;
    float*    Cg = sm + OFF_C + g*1056;
    unsigned* Pw = (unsigned*)sm + OFF_P + w*1088;
    float* statm = sm + OFF_SM;
    float* stats = sm + OFF_SS;
    int*   xm    = (int*)(sm + OFF_XM);
    int*   smg   = (int*)(sm + OFF_SMS) + g*32;

    // stage Q (tf32)
    #pragma unroll
    for (int i = 0; i < 8; i++){
        int id = tid + i*256;
        int r = id >> 6, c4 = (id & 63) << 2;
        float4 v = *(const float4*)(Qm + (b*LQ + l0 + r)*256 + c4);
        unsigned* d = &Qs[r*QK_STR + c4];
        d[0]=f2tf(v.x); d[1]=f2tf(v.y); d[2]=f2tf(v.z); d[3]=f2tf(v.w);
    }
    if (tid < 32) xm[tid] = xmask[b*LQ + l0 + tid];
    __syncthreads();

    float o[2][8][4];
    #pragma unroll
    for (int mt = 0; mt < 2; mt++)
        #pragma unroll
        for (int nt = 0; nt < 8; nt++)
            #pragma unroll
            for (int i = 0; i < 4; i++) o[mt][nt][i] = 0.f;
    float rmax[4] = {-1e30f,-1e30f,-1e30f,-1e30f};
    float rsum[4] = {0.f,0.f,0.f,0.f};

    for (int ti = 0; ti < 32; ti++){
        int s0 = (ti*2 + g)*32;
        if (g == 0) asm volatile("bar.sync 1, 128;" ::: "memory");
        else        asm volatile("bar.sync 2, 128;" ::: "memory");
        // K, V tiles (32 x 256)
        #pragma unroll
        for (int i = 0; i < 16; i++){
            int id = gt + i*128;
            int r = id >> 6, c4 = (id & 63) << 2;
            int grow = (b*LQ + s0 + r)*256 + c4;
            float4 vk = *(const float4*)(Km + grow);
            unsigned* dk = &Kg[r*QK_STR + c4];
            dk[0]=f2tf(vk.x); dk[1]=f2tf(vk.y); dk[2]=f2tf(vk.z); dk[3]=f2tf(vk.w);
            float4 vv = *(const float4*)(Vm + grow);
            unsigned* dv = &Vg[r*V_STR + c4];
            dv[0]=f2tf(vv.x); dv[1]=f2tf(vv.y); dv[2]=f2tf(vv.z); dv[3]=f2tf(vv.w);
        }
        // comp tile 32x32 (pre-scaled by 1/8)
        #pragma unroll
        for (int i = 0; i < 2; i++){
            int id = gt + i*128;
            int r = id >> 3, s4 = (id & 7) << 2;
            float4 v = *(const float4*)(comp + (b*LQ + l0 + r)*LQ + s0 + s4);
            float* d = &Cg[r*C_STR + s4];
            d[0]=v.x*0.125f; d[1]=v.y*0.125f; d[2]=v.z*0.125f; d[3]=v.w*0.125f;
        }
        if (gt < 32) smg[gt] = smask[b*LQ + s0 + gt];
        if (g == 0) asm volatile("bar.sync 1, 128;" ::: "memory");
        else        asm volatile("bar.sync 2, 128;" ::: "memory");

        // ---- QK^T : S[32l x 32s], K over 64 d of this head ----
        float S[2][4][4];
        #pragma unroll
        for (int mt = 0; mt < 2; mt++)
            #pragma unroll
            for (int nt = 0; nt < 4; nt++)
                #pragma unroll
                for (int i = 0; i < 4; i++) S[mt][nt][i] = 0.f;
        #pragma unroll
        for (int kk = 0; kk < 8; kk++){
            int k0 = dbase + kk*8;
            unsigned a[2][4], bf[4][2];
            #pragma unroll
            for (int mt = 0; mt < 2; mt++){
                int r = mt*16 + g4;
                a[mt][0] = Qs[r*QK_STR + k0 + tig];
                a[mt][1] = Qs[(r+8)*QK_STR + k0 + tig];
                a[mt][2] = Qs[r*QK_STR + k0 + tig + 4];
                a[mt][3] = Qs[(r+8)*QK_STR + k0 + tig + 4];
            }
            #pragma unroll
            for (int nt = 0; nt < 4; nt++){
                int s = nt*8 + g4;
                bf[nt][0] = Kg[s*QK_STR + k0 + tig];
                bf[nt][1] = Kg[s*QK_STR + k0 + tig + 4];
            }
            #pragma unroll
            for (int mt = 0; mt < 2; mt++)
                #pragma unroll
                for (int nt = 0; nt < 4; nt++)
                    mma8(S[mt][nt], a[mt], bf[nt]);
        }

        // ---- fixup + online softmax (warp-local rows) ----
        #pragma unroll
        for (int mt = 0; mt < 2; mt++){
            int rl = mt*16 + g4, rh = rl + 8;
            int xml = xm[rl], xmh = xm[rh];
            float tmaxl = -1e30f, tmaxh = -1e30f;
            #pragma unroll
            for (int nt = 0; nt < 4; nt++){
                int se = nt*8 + 2*tig, so = se + 1;
                int mse = smg[se], mso = smg[so];
                float v0 = (xml && !mse) ? -1e30f : S[mt][nt][0] * Cg[rl*C_STR + se];
                float v1 = (xml && !mso) ? -1e30f : S[mt][nt][1] * Cg[rl*C_STR + so];
                float v2 = (xmh && !mse) ? -1e30f : S[mt][nt][2] * Cg[rh*C_STR + se];
                float v3 = (xmh && !mso) ? -1e30f : S[mt][nt][3] * Cg[rh*C_STR + so];
                S[mt][nt][0]=v0; S[mt][nt][1]=v1; S[mt][nt][2]=v2; S[mt][nt][3]=v3;
                tmaxl = fmaxf(tmaxl, fmaxf(v0, v1));
                tmaxh = fmaxf(tmaxh, fmaxf(v2, v3));
            }
            tmaxl = fmaxf(tmaxl, __shfl_xor_sync(~0u, tmaxl, 1));
            tmaxl = fmaxf(tmaxl, __shfl_xor_sync(~0u, tmaxl, 2));
            tmaxh = fmaxf(tmaxh, __shfl_xor_sync(~0u, tmaxh, 1));
            tmaxh = fmaxf(tmaxh, __shfl_xor_sync(~0u, tmaxh, 2));
            int ril = mt*2, rih = mt*2 + 1;
            float ml = fmaxf(rmax[ril], tmaxl), mh = fmaxf(rmax[rih], tmaxh);
            float al = fast_exp(rmax[ril] - ml), ah = fast_exp(rmax[rih] - mh);
            rmax[ril] = ml; rmax[rih] = mh;
            float tsl = 0.f, tsh = 0.f;
            #pragma unroll
            for (int nt = 0; nt < 4; nt++){
                float p0 = fast_exp(S[mt][nt][0] - ml);
                float p1 = fast_exp(S[mt][nt][1] - ml);
                float p2 = fast_exp(S[mt][nt][2] - mh);
                float p3 = fast_exp(S[mt][nt][3] - mh);
                tsl += p0 + p1; tsh += p2 + p3;
                int se = nt*8 + 2*tig;
                *(uint2*)&Pw[rl*P_STR + se] = make_uint2(f2tf(p0), f2tf(p1));
                *(uint2*)&Pw[rh*P_STR + se] = make_uint2(f2tf(p2), f2tf(p3));
            }
            tsl += __shfl_xor_sync(~0u, tsl, 1); tsl += __shfl_xor_sync(~0u, tsl, 2);
            tsh += __shfl_xor_sync(~0u, tsh, 1); tsh += __shfl_xor_sync(~0u, tsh, 2);
            rsum[ril] = rsum[ril]*al + tsl;
            rsum[rih] = rsum[rih]*ah + tsh;
            #pragma unroll
            for (int nt = 0; nt < 8; nt++){
                o[mt][nt][0] *= al; o[mt][nt][1] *= al;
                o[mt][nt][2] *= ah; o[mt][nt][3] *= ah;
            }
        }
        __syncwarp();

        // ---- P @ V : o[32l x 64d] ----
        #pragma unroll
        for (int kk = 0; kk < 4; kk++){
            int k0 = kk*8;
            unsigned a[2][4], bf[8][2];
            #pragma unroll
            for (int mt = 0; mt < 2; mt++){
                int r = mt*16 + g4;
                a[mt][0] = Pw[r*P_STR + k0 + tig];
                a[mt][1] = Pw[(r+8)*P_STR + k0 + tig];
                a[mt][2] = Pw[r*P_STR + k0 + tig + 4];
                a[mt][3] = Pw[(r+8)*P_STR + k0 + tig + 4];
            }
            #pragma unroll
            for (int nt = 0; nt < 8; nt++){
                int d = dbase + nt*8 + g4;
                bf[nt][0] = Vg[(k0 + tig)*V_STR + d];
                bf[nt][1] = Vg[(k0 + tig + 4)*V_STR + d];
            }
            #pragma unroll
            for (int mt = 0; mt < 2; mt++)
                #pragma unroll
                for (int nt = 0; nt < 8; nt++)
                    mma8(o[mt][nt], a[mt], bf[nt]);
        }
        __syncwarp();
    }

    // ---- merge the two split-KV groups ----
    __syncthreads();
    if (tig == 0){
        #pragma unroll
        for (int mt = 0; mt < 2; mt++){
            int rl = mt*16 + g4;
            statm[(g*4+h)*32 + rl]   = rmax[mt*2];
            stats[(g*4+h)*32 + rl]   = rsum[mt*2];
            statm[(g*4+h)*32 + rl+8] = rmax[mt*2+1];
            stats[(g*4+h)*32 + rl+8] = rsum[mt*2+1];
        }
    }
    __syncthreads();
    float* Osm = sm + OFF_K;   // reuse K area: 32 x 260 fp32
    float myscale[4], invd[4];
    #pragma unroll
    for (int mt = 0; mt < 2; mt++)
        #pragma unroll
        for (int hb = 0; hb < 2; hb++){
            int r = mt*16 + g4 + hb*8;
            float m0 = statm[(0*4+h)*32 + r], m1 = statm[(1*4+h)*32 + r];
            float s0 = stats[(0*4+h)*32 + r], s1 = stats[(1*4+h)*32 + r];
            float m = fmaxf(m0, m1);
            float a0 = fast_exp(m0 - m), a1 = fast_exp(m1 - m);
            float den = s0*a0 + s1*a1;
            myscale[mt*2+hb] = (g == 0) ? a0 : a1;
            invd[mt*2+hb] = 1.0f / den;
        }
    if (g == 0){
        #pragma unroll
        for (int mt = 0; mt < 2; mt++)
            #pragma unroll
            for (int nt = 0; nt < 8; nt++){
                int rl = mt*16 + g4;
                int col = dbase + nt*8 + 2*tig;
                *(float2*)&Osm[rl*QK_STR + col] =
                    make_float2(o[mt][nt][0]*myscale[mt*2], o[mt][nt][1]*myscale[mt*2]);
                *(float2*)&Osm[(rl+8)*QK_STR + col] =
                    make_float2(o[mt][nt][2]*myscale[mt*2+1], o[mt][nt][3]*myscale[mt*2+1]);
            }
    }
    __syncthreads();
    if (g == 1){
        #pragma unroll
        for (int mt = 0; mt < 2; mt++)
            #pragma unroll
            for (int nt = 0; nt < 8; nt++){
                int rl = mt*16 + g4;
                int col = dbase + nt*8 + 2*tig;
                float2 q0 = *(float2*)&Osm[rl*QK_STR + col];
                float2 q1 = *(float2*)&Osm[(rl+8)*QK_STR + col];
                float2 r0 = make_float2((q0.x + o[mt][nt][0]*myscale[mt*2])*invd[mt*2],
                                        (q0.y + o[mt][nt][1]*myscale[mt*2])*invd[mt*2]);
                float2 r1 = make_float2((q1.x + o[mt][nt][2]*myscale[mt*2+1])*invd[mt*2+1],
                                        (q1.y + o[mt][nt][3]*myscale[mt*2+1])*invd[mt*2+1]);
                *(float2*)(O + (b*LQ + l0 + rl)*256 + col)     = r0;
                *(float2*)(O + (b*LQ + l0 + rl + 8)*256 + col) = r1;
            }
    }
}

// ---------------------------------------------------------------------------
extern "C" void kernel_launch(void* const* d_in, const int* in_sizes, int n_in,
                              void* d_out, int out_size)
{
    const float* x    = (const float*)d_in[0];
    const float* src  = (const float*)d_in[1];
    const float* xpe  = (const float*)d_in[2];
    const float* spe  = (const float*)d_in[3];
    const int* xmask  = (const int*)d_in[4];
    const int* smask  = (const int*)d_in[5];
    const float* comp = (const float*)d_in[6];
    const float* Wq   = (const float*)d_in[7];
    const float* Wk   = (const float*)d_in[8];
    const float* Wv   = (const float*)d_in[9];
    const float* Wmg  = (const float*)d_in[10];
    const float* Wm1  = (const float*)d_in[11];
    const float* Wm2  = (const float*)d_in[12];
    const float* ln1g = (const float*)d_in[13];
    const float* ln1b = (const float*)d_in[14];
    const float* ln2g = (const float*)d_in[15];
    const float* ln2b = (const float*)d_in[16];
    float* out = (float*)d_out;

    float *Qp, *Kp, *Vp, *Op;
    cudaGetSymbolAddress((void**)&Qp, g_Q);
    cudaGetSymbolAddress((void**)&Kp, g_K);
    cudaGetSymbolAddress((void**)&Vp, g_V);
    cudaGetSymbolAddress((void**)&Op, g_O);

    const int SM_GEMM = (64*AS_STR + 32*BS_STR) * 4;       // 43008
    const int SM_ATTN = ATTN_SMEM_WORDS * 4;               // 213120

    cudaFuncSetAttribute(k_attn, cudaFuncAttributeMaxDynamicSharedMemorySize, SM_ATTN);

    k_qkv <<<dim3(MROWS/64, 1, 3), 256, SM_GEMM>>>(x, xpe, src, spe, Wq, Wk, Wv);
    k_attn<<<dim3(LQ/32, BSZ),     256, SM_ATTN>>>(Qp, Kp, Vp, comp, xmask, smask, Op);
    k_merge<<<MROWS/64,            256, SM_GEMM>>>(Wmg, ln1g, ln1b);
    k_mlp1<<<dim3(MROWS/64, 2),    256, SM_GEMM>>>(x, Wm1);
    k_mlp2<<<MROWS/64,             256, SM_GEMM>>>(Wm2, ln2g, ln2b, x, out);
}

// round 4
// speedup vs baseline: 3.2079x; 1.1097x over previous
#include <cuda_runtime.h>
#include <cstdint>

#define BSZ 2
#define LQ 2048
#define DM 256
#define MROWS (BSZ*LQ)

// scratch
__device__ float g_Q[MROWS*DM];
__device__ float g_K[MROWS*DM];
__device__ float g_V[MROWS*DM];
__device__ float g_O[MROWS*DM];
__device__ float g_msg[MROWS*DM];
__device__ float g_hid[MROWS*2*DM];

// ---------------------------------------------------------------------------
__device__ __forceinline__ unsigned f2tf(float x){
    unsigned u; asm("cvt.rna.tf32.f32 %0,%1;" : "=r"(u) : "f"(x)); return u;
}
__device__ __forceinline__ void mma8(float* c, const unsigned* a, const unsigned* b){
    asm volatile("mma.sync.aligned.m16n8k8.row.col.f32.tf32.tf32.f32 "
        "{%0,%1,%2,%3},{%4,%5,%6,%7},{%8,%9},{%0,%1,%2,%3};"
        : "+f"(c[0]), "+f"(c[1]), "+f"(c[2]), "+f"(c[3])
        : "r"(a[0]), "r"(a[1]), "r"(a[2]), "r"(a[3]), "r"(b[0]), "r"(b[1]));
}
// e^x for x <= 0, FMA-pipe only (no MUFU). rel err ~2e-6.
__device__ __forceinline__ float fast_exp(float x){
    float y = x * 1.44269504f;
    y = fmaxf(y, -126.0f);
    float z = y + 12582912.0f;
    int   n = __float_as_int(z) - 0x4B400000;
    float f = y - (z - 12582912.0f);
    float p = 1.33336e-3f;
    p = fmaf(p, f, 9.61813e-3f);
    p = fmaf(p, f, 5.55041e-2f);
    p = fmaf(p, f, 2.40227e-1f);
    p = fmaf(p, f, 6.93147e-1f);
    p = fmaf(p, f, 1.0f);
    return p * __int_as_float((n + 127) << 23);
}

// ---------------------------------------------------------------------------
// tf32 GEMM: BM=32, BN=256, BK=32, 256 threads, double-buffered smem.
// 8 warps: wm = w>>2 (2), wn = w&3 (4); warp tile 16 x 64 (nt=8 m16n8 frags).
// ---------------------------------------------------------------------------
#define AM_PLAIN 0
#define AM_ADD   1
#define AM_CAT   2
#define EPI_NONE 0
#define EPI_RELU 1
#define EPI_LN   2
#define EPI_LNR  3

#define AS_STR 36
#define BS_STR 264
#define BUF_WORDS (32*AS_STR + 32*BS_STR)   // 9600
#define SM_GEMM (2*BUF_WORDS*4)             // 76800 bytes

template<int KD, int AM>
__device__ __forceinline__ void gload(const float* __restrict__ A1, const float* __restrict__ A2,
    const float* __restrict__ B, int ldb, int n0, int row0, int kc, int tid,
    float4& pa, float4* pb)
{
    int ar = tid >> 3, ac4 = (tid & 7) << 2;
    int col = kc*32 + ac4;
    if (AM == AM_ADD){
        float4 x1 = *(const float4*)(A1 + (row0+ar)*KD + col);
        float4 x2 = *(const float4*)(A2 + (row0+ar)*KD + col);
        pa = make_float4(x1.x+x2.x, x1.y+x2.y, x1.z+x2.z, x1.w+x2.w);
    } else if (AM == AM_CAT){
        const float* s = (col < 256) ? (A1 + (row0+ar)*256 + col)
                                     : (A2 + (row0+ar)*256 + (col-256));
        pa = *(const float4*)s;
    } else {
        pa = *(const float4*)(A1 + (row0+ar)*KD + col);
    }
    #pragma unroll
    for (int i = 0; i < 8; i++){
        int id = tid + i*256;
        int r = id >> 6, c4 = (id & 63) << 2;
        pb[i] = *(const float4*)(B + (kc*32 + r)*ldb + n0 + c4);
    }
}

__device__ __forceinline__ void sstore(unsigned* Abuf, unsigned* Bbuf, int tid,
    const float4& pa, const float4* pb)
{
    int ar = tid >> 3, ac4 = (tid & 7) << 2;
    unsigned* d = &Abuf[ar*AS_STR + ac4];
    d[0]=f2tf(pa.x); d[1]=f2tf(pa.y); d[2]=f2tf(pa.z); d[3]=f2tf(pa.w);
    #pragma unroll
    for (int i = 0; i < 8; i++){
        int id = tid + i*256;
        int r = id >> 6, c4 = (id & 63) << 2;
        unsigned* e = &Bbuf[r*BS_STR + c4];
        e[0]=f2tf(pb[i].x); e[1]=f2tf(pb[i].y); e[2]=f2tf(pb[i].z); e[3]=f2tf(pb[i].w);
    }
}

template<int KD, int AM, int EPI>
__device__ __forceinline__ void gemm_body(
    const float* __restrict__ A1, const float* __restrict__ A2,
    const float* __restrict__ B, int ldb, int n0,
    const float* __restrict__ gamma, const float* __restrict__ beta,
    const float* __restrict__ resid, float* __restrict__ C, int ldc)
{
    extern __shared__ unsigned smu[];
    const int KC = KD/32;
    int tid = threadIdx.x;
    int w = tid >> 5, lane = tid & 31;
    int wm = w >> 2, wn = w & 3;
    int g4 = lane >> 2, tig = lane & 3;
    int row0 = blockIdx.x * 32;

    float acc[8][4];
    #pragma unroll
    for (int nt = 0; nt < 8; nt++)
        #pragma unroll
        for (int i = 0; i < 4; i++) acc[nt][i] = 0.f;

    float4 pa, pb[8];
    gload<KD, AM>(A1, A2, B, ldb, n0, row0, 0, tid, pa, pb);
    sstore(smu, smu + 32*AS_STR, tid, pa, pb);
    __syncthreads();

    for (int kc = 0; kc < KC; kc++){
        unsigned* Abuf = smu + (kc & 1)*BUF_WORDS;
        unsigned* Bbuf = Abuf + 32*AS_STR;
        if (kc + 1 < KC)
            gload<KD, AM>(A1, A2, B, ldb, n0, row0, kc+1, tid, pa, pb);
        #pragma unroll
        for (int kk = 0; kk < 4; kk++){
            int k0 = kk*8;
            unsigned a[4], bf[2];
            int r = wm*16 + g4;
            a[0] = Abuf[r*AS_STR + k0 + tig];
            a[1] = Abuf[(r+8)*AS_STR + k0 + tig];
            a[2] = Abuf[r*AS_STR + k0 + tig + 4];
            a[3] = Abuf[(r+8)*AS_STR + k0 + tig + 4];
            #pragma unroll
            for (int nt = 0; nt < 8; nt++){
                int n = wn*64 + nt*8 + g4;
                bf[0] = Bbuf[(k0 + tig)*BS_STR + n];
                bf[1] = Bbuf[(k0 + tig + 4)*BS_STR + n];
                mma8(acc[nt], a, bf);
            }
        }
        if (kc + 1 < KC){
            unsigned* An = smu + ((kc+1) & 1)*BUF_WORDS;
            sstore(An, An + 32*AS_STR, tid, pa, pb);
        }
        __syncthreads();
    }

    if (EPI == EPI_NONE || EPI == EPI_RELU){
        int rl = row0 + wm*16 + g4;
        #pragma unroll
        for (int nt = 0; nt < 8; nt++){
            int col = n0 + wn*64 + nt*8 + 2*tig;
            float v0 = acc[nt][0], v1 = acc[nt][1];
            float v2 = acc[nt][2], v3 = acc[nt][3];
            if (EPI == EPI_RELU){
                v0=fmaxf(v0,0.f); v1=fmaxf(v1,0.f); v2=fmaxf(v2,0.f); v3=fmaxf(v3,0.f);
            }
            *(float2*)(C + rl*ldc + col)     = make_float2(v0, v1);
            *(float2*)(C + (rl+8)*ldc + col) = make_float2(v2, v3);
        }
    } else {
        float2* red = (float2*)smu;   // red[32][4]
        float s1[2] = {0,0}, s2[2] = {0,0};
        #pragma unroll
        for (int nt = 0; nt < 8; nt++){
            float c0=acc[nt][0], c1=acc[nt][1], c2=acc[nt][2], c3=acc[nt][3];
            s1[0] += c0+c1; s2[0] += c0*c0 + c1*c1;
            s1[1] += c2+c3; s2[1] += c2*c2 + c3*c3;
        }
        #pragma unroll
        for (int hb = 0; hb < 2; hb++){
            float v1 = s1[hb], v2 = s2[hb];
            v1 += __shfl_xor_sync(~0u, v1, 1); v1 += __shfl_xor_sync(~0u, v1, 2);
            v2 += __shfl_xor_sync(~0u, v2, 1); v2 += __shfl_xor_sync(~0u, v2, 2);
            if (tig == 0){
                int r = wm*16 + g4 + hb*8;
                red[r*4 + wn] = make_float2(v1, v2);
            }
        }
        __syncthreads();
        #pragma unroll
        for (int hb = 0; hb < 2; hb++){
            int r = wm*16 + g4 + hb*8;
            float S1 = 0.f, S2 = 0.f;
            #pragma unroll
            for (int j = 0; j < 4; j++){ float2 e = red[r*4+j]; S1 += e.x; S2 += e.y; }
            float mean = S1 * (1.f/256.f);
            float var  = S2 * (1.f/256.f) - mean*mean;
            float inv  = rsqrtf(var + 1e-5f);
            int grow = row0 + r;
            #pragma unroll
            for (int nt = 0; nt < 8; nt++){
                int col = wn*64 + nt*8 + 2*tig;
                float c0 = acc[nt][hb*2], c1 = acc[nt][hb*2+1];
                float o0 = (c0 - mean)*inv*gamma[col]   + beta[col];
                float o1 = (c1 - mean)*inv*gamma[col+1] + beta[col+1];
                if (EPI == EPI_LNR){
                    o0 += resid[grow*256 + col];
                    o1 += resid[grow*256 + col + 1];
                }
                *(float2*)(C + grow*ldc + col) = make_float2(o0, o1);
            }
        }
    }
}

__global__ void __launch_bounds__(256) k_qkv(
    const float* x, const float* xpe, const float* src, const float* spe,
    const float* Wq, const float* Wk, const float* Wv)
{
    if (blockIdx.z == 0)      gemm_body<256, AM_ADD,   EPI_NONE>(x,   xpe, Wq, 256, 0, 0,0,0, g_Q, 256);
    else if (blockIdx.z == 1) gemm_body<256, AM_ADD,   EPI_NONE>(src, spe, Wk, 256, 0, 0,0,0, g_K, 256);
    else                      gemm_body<256, AM_PLAIN, EPI_NONE>(src, 0,   Wv, 256, 0, 0,0,0, g_V, 256);
}
__global__ void __launch_bounds__(256) k_merge(const float* Wmg, const float* gg, const float* bb){
    gemm_body<256, AM_PLAIN, EPI_LN>(g_O, 0, Wmg, 256, 0, gg, bb, 0, g_msg, 256);
}
__global__ void __launch_bounds__(256) k_mlp1(const float* x, const float* Wm1){
    gemm_body<512, AM_CAT, EPI_RELU>(x, g_msg, Wm1, 512, blockIdx.y*256, 0,0,0, g_hid, 512);
}
__global__ void __launch_bounds__(256) k_mlp2(const float* Wm2, const float* gg, const float* bb,
                                              const float* x, float* out){
    gemm_body<512, AM_PLAIN, EPI_LNR>(g_hid, 0, Wm2, 256, 0, gg, bb, x, out, 256);
}

// ---------------------------------------------------------------------------
// Flash attention, tf32 mma. CTA = (b, 32 l-rows), 8 warps.
// warp w: head h = w&3, group g = w>>2. Groups split-KV (s-tiles g, g+2, ...)
// ---------------------------------------------------------------------------
#define QK_STR 260
#define V_STR  264
#define C_STR  33
#define P_STR  34

#define OFF_K   8320
#define OFF_V   24960
#define OFF_C   41856
#define OFF_P   43968
#define OFF_SM  52672
#define OFF_SS  52928
#define OFF_XM  53184
#define OFF_SMS 53216
#define ATTN_SMEM_WORDS 53280

__global__ void __launch_bounds__(256) k_attn(
    const float* __restrict__ Qm, const float* __restrict__ Km, const float* __restrict__ Vm,
    const float* __restrict__ comp, const int* __restrict__ xmask, const int* __restrict__ smask,
    float* __restrict__ O)
{
    extern __shared__ float sm[];
    int tid = threadIdx.x;
    int w = tid >> 5, lane = tid & 31;
    int h = w & 3, g = w >> 2;
    int g4 = lane >> 2, tig = lane & 3;
    int gt = tid & 127;
    int b = blockIdx.y, l0 = blockIdx.x * 32;
    int dbase = h*64;

    unsigned* Qs = (unsigned*)sm;
    unsigned* Kg = (unsigned*)sm + OFF_K + g*8320;
    unsigned* Vg = (unsigned*)sm + OFF_V + g*8448;
    float*    Cg = sm + OFF_C + g*1056;
    unsigned* Pw = (unsigned*)sm + OFF_P + w*1088;
    float* statm = sm + OFF_SM;
    float* stats = sm + OFF_SS;
    int*   xm    = (int*)(sm + OFF_XM);
    int*   smg   = (int*)(sm + OFF_SMS) + g*32;

    #pragma unroll
    for (int i = 0; i < 8; i++){
        int id = tid + i*256;
        int r = id >> 6, c4 = (id & 63) << 2;
        float4 v = *(const float4*)(Qm + (b*LQ + l0 + r)*256 + c4);
        unsigned* d = &Qs[r*QK_STR + c4];
        d[0]=f2tf(v.x); d[1]=f2tf(v.y); d[2]=f2tf(v.z); d[3]=f2tf(v.w);
    }
    if (tid < 32) xm[tid] = xmask[b*LQ + l0 + tid];
    __syncthreads();

    float o[2][8][4];
    #pragma unroll
    for (int mt = 0; mt < 2; mt++)
        #pragma unroll
        for (int nt = 0; nt < 8; nt++)
            #pragma unroll
            for (int i = 0; i < 4; i++) o[mt][nt][i] = 0.f;
    float rmax[4] = {-1e30f,-1e30f,-1e30f,-1e30f};
    float rsum[4] = {0.f,0.f,0.f,0.f};

    for (int ti = 0; ti < 32; ti++){
        int s0 = (ti*2 + g)*32;
        if (g == 0) asm volatile("bar.sync 1, 128;" ::: "memory");
        else        asm volatile("bar.sync 2, 128;" ::: "memory");
        #pragma unroll
        for (int i = 0; i < 16; i++){
            int id = gt + i*128;
            int r = id >> 6, c4 = (id & 63) << 2;
            int grow = (b*LQ + s0 + r)*256 + c4;
            float4 vk = *(const float4*)(Km + grow);
            unsigned* dk = &Kg[r*QK_STR + c4];
            dk[0]=f2tf(vk.x); dk[1]=f2tf(vk.y); dk[2]=f2tf(vk.z); dk[3]=f2tf(vk.w);
            float4 vv = *(const float4*)(Vm + grow);
            unsigned* dv = &Vg[r*V_STR + c4];
            dv[0]=f2tf(vv.x); dv[1]=f2tf(vv.y); dv[2]=f2tf(vv.z); dv[3]=f2tf(vv.w);
        }
        #pragma unroll
        for (int i = 0; i < 2; i++){
            int id = gt + i*128;
            int r = id >> 3, s4 = (id & 7) << 2;
            float4 v = *(const float4*)(comp + (b*LQ + l0 + r)*LQ + s0 + s4);
            float* d = &Cg[r*C_STR + s4];
            d[0]=v.x*0.125f; d[1]=v.y*0.125f; d[2]=v.z*0.125f; d[3]=v.w*0.125f;
        }
        if (gt < 32) smg[gt] = smask[b*LQ + s0 + gt];
        if (g == 0) asm volatile("bar.sync 1, 128;" ::: "memory");
        else        asm volatile("bar.sync 2, 128;" ::: "memory");

        float S[2][4][4];
        #pragma unroll
        for (int mt = 0; mt < 2; mt++)
            #pragma unroll
            for (int nt = 0; nt < 4; nt++)
                #pragma unroll
                for (int i = 0; i < 4; i++) S[mt][nt][i] = 0.f;
        #pragma unroll
        for (int kk = 0; kk < 8; kk++){
            int k0 = dbase + kk*8;
            unsigned a[2][4], bf[4][2];
            #pragma unroll
            for (int mt = 0; mt < 2; mt++){
                int r = mt*16 + g4;
                a[mt][0] = Qs[r*QK_STR + k0 + tig];
                a[mt][1] = Qs[(r+8)*QK_STR + k0 + tig];
                a[mt][2] = Qs[r*QK_STR + k0 + tig + 4];
                a[mt][3] = Qs[(r+8)*QK_STR + k0 + tig + 4];
            }
            #pragma unroll
            for (int nt = 0; nt < 4; nt++){
                int s = nt*8 + g4;
                bf[nt][0] = Kg[s*QK_STR + k0 + tig];
                bf[nt][1] = Kg[s*QK_STR + k0 + tig + 4];
            }
            #pragma unroll
            for (int mt = 0; mt < 2; mt++)
                #pragma unroll
                for (int nt = 0; nt < 4; nt++)
                    mma8(S[mt][nt], a[mt], bf[nt]);
        }

        #pragma unroll
        for (int mt = 0; mt < 2; mt++){
            int rl = mt*16 + g4, rh = rl + 8;
            int xml = xm[rl], xmh = xm[rh];
            float tmaxl = -1e30f, tmaxh = -1e30f;
            #pragma unroll
            for (int nt = 0; nt < 4; nt++){
                int se = nt*8 + 2*tig, so = se + 1;
                int mse = smg[se], mso = smg[so];
                float v0 = (xml && !mse) ? -1e30f : S[mt][nt][0] * Cg[rl*C_STR + se];
                float v1 = (xml && !mso) ? -1e30f : S[mt][nt][1] * Cg[rl*C_STR + so];
                float v2 = (xmh && !mse) ? -1e30f : S[mt][nt][2] * Cg[rh*C_STR + se];
                float v3 = (xmh && !mso) ? -1e30f : S[mt][nt][3] * Cg[rh*C_STR + so];
                S[mt][nt][0]=v0; S[mt][nt][1]=v1; S[mt][nt][2]=v2; S[mt][nt][3]=v3;
                tmaxl = fmaxf(tmaxl, fmaxf(v0, v1));
                tmaxh = fmaxf(tmaxh, fmaxf(v2, v3));
            }
            tmaxl = fmaxf(tmaxl, __shfl_xor_sync(~0u, tmaxl, 1));
            tmaxl = fmaxf(tmaxl, __shfl_xor_sync(~0u, tmaxl, 2));
            tmaxh = fmaxf(tmaxh, __shfl_xor_sync(~0u, tmaxh, 1));
            tmaxh = fmaxf(tmaxh, __shfl_xor_sync(~0u, tmaxh, 2));
            int ril = mt*2, rih = mt*2 + 1;
            float ml = fmaxf(rmax[ril], tmaxl), mh = fmaxf(rmax[rih], tmaxh);
            float al = fast_exp(rmax[ril] - ml), ah = fast_exp(rmax[rih] - mh);
            rmax[ril] = ml; rmax[rih] = mh;
            float tsl = 0.f, tsh = 0.f;
            #pragma unroll
            for (int nt = 0; nt < 4; nt++){
                float p0 = fast_exp(S[mt][nt][0] - ml);
                float p1 = fast_exp(S[mt][nt][1] - ml);
                float p2 = fast_exp(S[mt][nt][2] - mh);
                float p3 = fast_exp(S[mt][nt][3] - mh);
                tsl += p0 + p1; tsh += p2 + p3;
                int se = nt*8 + 2*tig;
                *(uint2*)&Pw[rl*P_STR + se] = make_uint2(f2tf(p0), f2tf(p1));
                *(uint2*)&Pw[rh*P_STR + se] = make_uint2(f2tf(p2), f2tf(p3));
            }
            tsl += __shfl_xor_sync(~0u, tsl, 1); tsl += __shfl_xor_sync(~0u, tsl, 2);
            tsh += __shfl_xor_sync(~0u, tsh, 1); tsh += __shfl_xor_sync(~0u, tsh, 2);
            rsum[ril] = rsum[ril]*al + tsl;
            rsum[rih] = rsum[rih]*ah + tsh;
            #pragma unroll
            for (int nt = 0; nt < 8; nt++){
                o[mt][nt][0] *= al; o[mt][nt][1] *= al;
                o[mt][nt][2] *= ah; o[mt][nt][3] *= ah;
            }
        }
        __syncwarp();

        #pragma unroll
        for (int kk = 0; kk < 4; kk++){
            int k0 = kk*8;
            unsigned a[2][4], bf[8][2];
            #pragma unroll
            for (int mt = 0; mt < 2; mt++){
                int r = mt*16 + g4;
                a[mt][0] = Pw[r*P_STR + k0 + tig];
                a[mt][1] = Pw[(r+8)*P_STR + k0 + tig];
                a[mt][2] = Pw[r*P_STR + k0 + tig + 4];
                a[mt][3] = Pw[(r+8)*P_STR + k0 + tig + 4];
            }
            #pragma unroll
            for (int nt = 0; nt < 8; nt++){
                int d = dbase + nt*8 + g4;
                bf[nt][0] = Vg[(k0 + tig)*V_STR + d];
                bf[nt][1] = Vg[(k0 + tig + 4)*V_STR + d];
            }
            #pragma unroll
            for (int mt = 0; mt < 2; mt++)
                #pragma unroll
                for (int nt = 0; nt < 8; nt++)
                    mma8(o[mt][nt], a[mt], bf[nt]);
        }
        __syncwarp();
    }

    __syncthreads();
    if (tig == 0){
        #pragma unroll
        for (int mt = 0; mt < 2; mt++){
            int rl = mt*16 + g4;
            statm[(g*4+h)*32 + rl]   = rmax[mt*2];
            stats[(g*4+h)*32 + rl]   = rsum[mt*2];
            statm[(g*4+h)*32 + rl+8] = rmax[mt*2+1];
            stats[(g*4+h)*32 + rl+8] = rsum[mt*2+1];
        }
    }
    __syncthreads();
    float* Osm = sm + OFF_K;
    float myscale[4], invd[4];
    #pragma unroll
    for (int mt = 0; mt < 2; mt++)
        #pragma unroll
        for (int hb = 0; hb < 2; hb++){
            int r = mt*16 + g4 + hb*8;
            float m0 = statm[(0*4+h)*32 + r], m1 = statm[(1*4+h)*32 + r];
            float s0 = stats[(0*4+h)*32 + r], s1 = stats[(1*4+h)*32 + r];
            float m = fmaxf(m0, m1);
            float a0 = fast_exp(m0 - m), a1 = fast_exp(m1 - m);
            float den = s0*a0 + s1*a1;
            myscale[mt*2+hb] = (g == 0) ? a0 : a1;
            invd[mt*2+hb] = 1.0f / den;
        }
    if (g == 0){
        #pragma unroll
        for (int mt = 0; mt < 2; mt++)
            #pragma unroll
            for (int nt = 0; nt < 8; nt++){
                int rl = mt*16 + g4;
                int col = dbase + nt*8 + 2*tig;
                *(float2*)&Osm[rl*QK_STR + col] =
                    make_float2(o[mt][nt][0]*myscale[mt*2], o[mt][nt][1]*myscale[mt*2]);
                *(float2*)&Osm[(rl+8)*QK_STR + col] =
                    make_float2(o[mt][nt][2]*myscale[mt*2+1], o[mt][nt][3]*myscale[mt*2+1]);
            }
    }
    __syncthreads();
    if (g == 1){
        #pragma unroll
        for (int mt = 0; mt < 2; mt++)
            #pragma unroll
            for (int nt = 0; nt < 8; nt++){
                int rl = mt*16 + g4;
                int col = dbase + nt*8 + 2*tig;
                float2 q0 = *(float2*)&Osm[rl*QK_STR + col];
                float2 q1 = *(float2*)&Osm[(rl+8)*QK_STR + col];
                float2 r0 = make_float2((q0.x + o[mt][nt][0]*myscale[mt*2])*invd[mt*2],
                                        (q0.y + o[mt][nt][1]*myscale[mt*2])*invd[mt*2]);
                float2 r1 = make_float2((q1.x + o[mt][nt][2]*myscale[mt*2+1])*invd[mt*2+1],
                                        (q1.y + o[mt][nt][3]*myscale[mt*2+1])*invd[mt*2+1]);
                *(float2*)(O + (b*LQ + l0 + rl)*256 + col)     = r0;
                *(float2*)(O + (b*LQ + l0 + rl + 8)*256 + col) = r1;
            }
    }
}

// ---------------------------------------------------------------------------
extern "C" void kernel_launch(void* const* d_in, const int* in_sizes, int n_in,
                              void* d_out, int out_size)
{
    const float* x    = (const float*)d_in[0];
    const float* src  = (const float*)d_in[1];
    const float* xpe  = (const float*)d_in[2];
    const float* spe  = (const float*)d_in[3];
    const int* xmask  = (const int*)d_in[4];
    const int* smask  = (const int*)d_in[5];
    const float* comp = (const float*)d_in[6];
    const float* Wq   = (const float*)d_in[7];
    const float* Wk   = (const float*)d_in[8];
    const float* Wv   = (const float*)d_in[9];
    const float* Wmg  = (const float*)d_in[10];
    const float* Wm1  = (const float*)d_in[11];
    const float* Wm2  = (const float*)d_in[12];
    const float* ln1g = (const float*)d_in[13];
    const float* ln1b = (const float*)d_in[14];
    const float* ln2g = (const float*)d_in[15];
    const float* ln2b = (const float*)d_in[16];
    float* out = (float*)d_out;

    float *Qp, *Kp, *Vp, *Op;
    cudaGetSymbolAddress((void**)&Qp, g_Q);
    cudaGetSymbolAddress((void**)&Kp, g_K);
    cudaGetSymbolAddress((void**)&Vp, g_V);
    cudaGetSymbolAddress((void**)&Op, g_O);

    const int SM_ATTN = ATTN_SMEM_WORDS * 4;

    cudaFuncSetAttribute(k_qkv,   cudaFuncAttributeMaxDynamicSharedMemorySize, SM_GEMM);
    cudaFuncSetAttribute(k_merge, cudaFuncAttributeMaxDynamicSharedMemorySize, SM_GEMM);
    cudaFuncSetAttribute(k_mlp1,  cudaFuncAttributeMaxDynamicSharedMemorySize, SM_GEMM);
    cudaFuncSetAttribute(k_mlp2,  cudaFuncAttributeMaxDynamicSharedMemorySize, SM_GEMM);
    cudaFuncSetAttribute(k_attn,  cudaFuncAttributeMaxDynamicSharedMemorySize, SM_ATTN);

    k_qkv <<<dim3(MROWS/32, 1, 3), 256, SM_GEMM>>>(x, xpe, src, spe, Wq, Wk, Wv);
    k_attn<<<dim3(LQ/32, BSZ),     256, SM_ATTN>>>(Qp, Kp, Vp, comp, xmask, smask, Op);
    k_merge<<<MROWS/32,            256, SM_GEMM>>>(Wmg, ln1g, ln1b);
    k_mlp1<<<dim3(MROWS/32, 2),    256, SM_GEMM>>>(x, Wm1);
    k_mlp2<<<MROWS/32,             256, SM_GEMM>>>(Wm2, ln2g, ln2b, x, out);
}